// round 1
// baseline (speedup 1.0000x reference)
#include <cuda_runtime.h>
#include <cstdint>

// Shapes (fixed by the problem)
#define B_   16
#define T_   12
#define N_   1000
#define F_   64
#define KC_  3
#define OUT_ 64

// Flattened contraction dim for the spatial GEMM: kj = k*1000 + j in [0, 3000)
#define KJ_  (KC_ * N_)          // 3000
#define TO_  (T_ * OUT_)         // 768

// Scratch: y[b][kj][to]  (b * 3000 * 768 floats)  ~147.5 MB
__device__ float g_y[(size_t)B_ * KJ_ * TO_];

// ---------------------------------------------------------------------------
// Kernel A: y[b][k*1000+j][t*64+o] = sum_f x[b,t,j,f] * Theta[k,f,o]
// Block = 256 threads = 16 rows x 16 (each thread does 4 consecutive o).
// Theta (3*64*64 floats = 48 KB) lives in static shared.
// ---------------------------------------------------------------------------
__global__ __launch_bounds__(256) void k_feature(
    const float* __restrict__ x,      // (B,T,N,F)
    const float* __restrict__ Theta)  // (K,F,OUT)
{
    __shared__ float Th[KC_ * F_ * OUT_];   // 49152 bytes
    const int tid = threadIdx.x;
    #pragma unroll
    for (int i = tid; i < KC_ * F_ * OUT_; i += 256) Th[i] = Theta[i];
    __syncthreads();

    const int row = blockIdx.x * 16 + (tid >> 4);    // row = (b*T + t)*N + j
    const int o4  = (tid & 15) * 4;

    const float* __restrict__ xr = x + (size_t)row * F_;

    float acc[KC_][4];
    #pragma unroll
    for (int k = 0; k < KC_; k++)
        #pragma unroll
        for (int n = 0; n < 4; n++) acc[k][n] = 0.f;

    #pragma unroll 8
    for (int f = 0; f < F_; f++) {
        const float xv = __ldg(xr + f);   // warp-uniform-ish (2 rows/warp) -> broadcast
        #pragma unroll
        for (int k = 0; k < KC_; k++) {
            const float4 th = *(const float4*)&Th[(k * F_ + f) * OUT_ + o4];
            acc[k][0] += xv * th.x;
            acc[k][1] += xv * th.y;
            acc[k][2] += xv * th.z;
            acc[k][3] += xv * th.w;
        }
    }

    // Decompose row -> (b, t, j) and scatter to y[b][k*1000+j][t*64+o]
    const int b  = row / (T_ * N_);
    const int tj = row % (T_ * N_);
    const int t  = tj / N_;
    const int j  = tj % N_;

    const size_t base = (size_t)b * KJ_ * TO_ + (size_t)j * TO_ + t * OUT_ + o4;
    #pragma unroll
    for (int k = 0; k < KC_; k++) {
        float4 v;
        v.x = acc[k][0]; v.y = acc[k][1]; v.z = acc[k][2]; v.w = acc[k][3];
        *(float4*)&g_y[base + (size_t)k * N_ * TO_] = v;
    }
}

// ---------------------------------------------------------------------------
// Kernel B: per batch b, GEMM
//   out[b, i, to] = relu( sum_kj  (cheb[kj*1000+i] * SAtt[b, kj%1000, i]) * y[b][kj][to] )
// M=1000 (i, padded to 1024), K=3000 (kj), N=768 (to).
// Classic SGEMM: BM=BN=128, BK=8, 256 threads, 8x8 micro-tile.
// ---------------------------------------------------------------------------
#define BM 128
#define BN 128
#define BK 8

__global__ __launch_bounds__(256, 2) void k_spatial(
    const float* __restrict__ SAtt,   // (B,N,N)
    const float* __restrict__ cheb,   // (K,N,N) == (3000, 1000) flattened
    float* __restrict__ out)          // (B,T,N,OUT)
{
    __shared__ float As[BK][BM];
    __shared__ float Bs[BK][BN];

    const int b  = blockIdx.z;
    const int i0 = blockIdx.y * BM;
    const int n0 = blockIdx.x * BN;

    const int tid = threadIdx.x;
    const int tx = tid & 15;          // n direction (8 cols each)
    const int ty = tid >> 4;          // m direction (8 rows each)

    const float* __restrict__ satt_b = SAtt + (size_t)b * N_ * N_;
    const float* __restrict__ y_b    = g_y + (size_t)b * KJ_ * TO_;

    float c[8][8];
    #pragma unroll
    for (int m = 0; m < 8; m++)
        #pragma unroll
        for (int n = 0; n < 8; n++) c[m][n] = 0.f;

    for (int p = 0; p < KJ_; p += BK) {
        // Cooperative load of A (formed on the fly) and B tiles.
        // 1024 elements each, 256 threads -> 4 per thread, i/to contiguous.
        #pragma unroll
        for (int l = 0; l < 4; l++) {
            const int idx  = tid + l * 256;
            const int kj_l = idx >> 7;       // 0..7
            const int e_l  = idx & 127;      // 0..127
            const int kj   = p + kj_l;

            // A element: cheb[kj,i] * SAtt[b, j, i],  j = kj % 1000
            const int i = i0 + e_l;
            float av = 0.f;
            if (i < N_) {
                const int k = (kj >= 2 * N_) ? 2 : (kj >= N_ ? 1 : 0);
                const int j = kj - k * N_;
                av = __ldg(cheb + (size_t)kj * N_ + i) *
                     __ldg(satt_b + (size_t)j * N_ + i);
            }
            As[kj_l][e_l] = av;

            // B element: y[b][kj][n0 + e_l]  (TO_=768 divisible by BN)
            Bs[kj_l][e_l] = __ldg(y_b + (size_t)kj * TO_ + n0 + e_l);
        }
        __syncthreads();

        #pragma unroll
        for (int kk = 0; kk < BK; kk++) {
            float a[8], bb[8];
            *(float4*)(a)     = *(const float4*)&As[kk][ty * 8];
            *(float4*)(a + 4) = *(const float4*)&As[kk][ty * 8 + 4];
            *(float4*)(bb)     = *(const float4*)&Bs[kk][tx * 8];
            *(float4*)(bb + 4) = *(const float4*)&Bs[kk][tx * 8 + 4];
            #pragma unroll
            for (int m = 0; m < 8; m++)
                #pragma unroll
                for (int n = 0; n < 8; n++)
                    c[m][n] += a[m] * bb[n];
        }
        __syncthreads();
    }

    // Epilogue: to = n0 + tx*8 + {0..7}; t constant within the 8 (aligned).
    const int to0 = n0 + tx * 8;
    const int t   = to0 / OUT_;
    const int oo  = to0 % OUT_;

    #pragma unroll
    for (int m = 0; m < 8; m++) {
        const int i = i0 + ty * 8 + m;
        if (i < N_) {
            const size_t addr = (size_t)b * (T_ * N_ * OUT_) +
                                (size_t)t * (N_ * OUT_) +
                                (size_t)i * OUT_ + oo;
            float4 v0, v1;
            v0.x = fmaxf(c[m][0], 0.f); v0.y = fmaxf(c[m][1], 0.f);
            v0.z = fmaxf(c[m][2], 0.f); v0.w = fmaxf(c[m][3], 0.f);
            v1.x = fmaxf(c[m][4], 0.f); v1.y = fmaxf(c[m][5], 0.f);
            v1.z = fmaxf(c[m][6], 0.f); v1.w = fmaxf(c[m][7], 0.f);
            *(float4*)&out[addr]     = v0;
            *(float4*)&out[addr + 4] = v1;
        }
    }
}

// ---------------------------------------------------------------------------
// Launch: inputs per metadata order: x, SAtt, cheb, Theta. Output float32.
// ---------------------------------------------------------------------------
extern "C" void kernel_launch(void* const* d_in, const int* in_sizes, int n_in,
                              void* d_out, int out_size)
{
    const float* x     = (const float*)d_in[0];
    const float* SAtt  = (const float*)d_in[1];
    const float* cheb  = (const float*)d_in[2];
    const float* Theta = (const float*)d_in[3];
    float* out = (float*)d_out;

    // Kernel A: 192000 rows / 16 per block
    k_feature<<<(B_ * T_ * N_) / 16, 256>>>(x, Theta);

    // Kernel B: grid (768/BN, ceil(1000/BM), B)
    dim3 grid(TO_ / BN, (N_ + BM - 1) / BM, B_);
    k_spatial<<<grid, 256>>>(SAtt, cheb, out);
}

// round 2
// speedup vs baseline: 2.6278x; 2.6278x over previous
#include <cuda_runtime.h>
#include <cstdint>

// Shapes (fixed by the problem)
#define B_   16
#define T_   12
#define N_   1000
#define F_   64
#define KC_  3
#define OUT_ 64

#define KJ_   3000            // contraction dim kj = k*1000 + j
#define KJP_  3008            // padded to multiple of 32
#define MP_   1024            // i padded
#define TO_   768             // t*64 + o

// Scratch (zero-initialized at module load; pad regions never written -> stay 0)
__device__ float g_y [(size_t)B_ * KJ_ * TO_];    // y[b][kj][to]
__device__ float g_yT[(size_t)B_ * TO_ * KJP_];   // yT[b][to][kjp]  (tf32-rounded)
__device__ float g_AT[(size_t)B_ * MP_ * KJP_];   // AT[b][i][kjp]   (tf32-rounded)

__device__ __forceinline__ float to_tf32(float v) {
    uint32_t u;
    asm("cvt.rna.tf32.f32 %0, %1;" : "=r"(u) : "f"(v));
    return __uint_as_float(u);
}

// ---------------------------------------------------------------------------
// Kernel 1: y[b][k*1000+j][t*64+o] = sum_f x[b,t,j,f] * Theta[k,f,o]
// (unchanged from round 1 — known good)
// ---------------------------------------------------------------------------
__global__ __launch_bounds__(256) void k_feature(
    const float* __restrict__ x,      // (B,T,N,F)
    const float* __restrict__ Theta)  // (K,F,OUT)
{
    __shared__ float Th[KC_ * F_ * OUT_];   // 49152 bytes
    const int tid = threadIdx.x;
    for (int i = tid; i < KC_ * F_ * OUT_; i += 256) Th[i] = Theta[i];
    __syncthreads();

    const int row = blockIdx.x * 16 + (tid >> 4);    // (b*T + t)*N + j
    const int o4  = (tid & 15) * 4;

    const float* __restrict__ xr = x + (size_t)row * F_;

    float acc[KC_][4];
    #pragma unroll
    for (int k = 0; k < KC_; k++)
        #pragma unroll
        for (int n = 0; n < 4; n++) acc[k][n] = 0.f;

    #pragma unroll 8
    for (int f = 0; f < F_; f++) {
        const float xv = __ldg(xr + f);
        #pragma unroll
        for (int k = 0; k < KC_; k++) {
            const float4 th = *(const float4*)&Th[(k * F_ + f) * OUT_ + o4];
            acc[k][0] += xv * th.x;
            acc[k][1] += xv * th.y;
            acc[k][2] += xv * th.z;
            acc[k][3] += xv * th.w;
        }
    }

    const int b  = row / (T_ * N_);
    const int tj = row % (T_ * N_);
    const int t  = tj / N_;
    const int j  = tj % N_;

    const size_t base = (size_t)b * KJ_ * TO_ + (size_t)j * TO_ + t * OUT_ + o4;
    #pragma unroll
    for (int k = 0; k < KC_; k++) {
        float4 v;
        v.x = acc[k][0]; v.y = acc[k][1]; v.z = acc[k][2]; v.w = acc[k][3];
        *(float4*)&g_y[base + (size_t)k * N_ * TO_] = v;
    }
}

// ---------------------------------------------------------------------------
// Kernel 2: yT[b][to][kj] = tf32( y[b][kj][to] )   (tiled transpose)
// ---------------------------------------------------------------------------
__global__ __launch_bounds__(256) void k_transpose_y()
{
    __shared__ float tile[32][33];
    const int b   = blockIdx.z;
    const int kj0 = blockIdx.x * 32;
    const int to0 = blockIdx.y * 32;
    const int tx = threadIdx.x & 31;
    const int ty = threadIdx.x >> 5;   // 0..7

    const float* __restrict__ yp = g_y + (size_t)b * KJ_ * TO_;
    #pragma unroll
    for (int r = 0; r < 4; r++) {
        int kj = kj0 + ty + r * 8;
        if (kj < KJ_)
            tile[ty + r * 8][tx] = yp[(size_t)kj * TO_ + to0 + tx];
    }
    __syncthreads();
    float* __restrict__ ytp = g_yT + (size_t)b * TO_ * KJP_;
    #pragma unroll
    for (int r = 0; r < 4; r++) {
        int to = to0 + ty + r * 8;
        int kj = kj0 + tx;
        if (kj < KJ_)
            ytp[(size_t)to * KJP_ + kj] = to_tf32(tile[tx][ty + r * 8]);
    }
}

// ---------------------------------------------------------------------------
// Kernel 3: AT[b][i][kj] = tf32( cheb[kj,i] * SAtt[b, kj%1000, i] )
// Transposed via padded smem. i>=1000 / kj>=3000 regions left untouched (zero).
// ---------------------------------------------------------------------------
__global__ __launch_bounds__(256) void k_buildA(
    const float* __restrict__ SAtt,   // (B,N,N)
    const float* __restrict__ cheb)   // (K,N,N)
{
    __shared__ float buf[256][33];    // [kj-local][i-local(32)]
    const int b    = blockIdx.z;
    const int i0   = blockIdx.y * 32;
    const int kjc  = blockIdx.x * 256;
    const int lane = threadIdx.x & 31;
    const int w    = threadIdx.x >> 5;
    const int i    = i0 + lane;

    const float* __restrict__ sb = SAtt + (size_t)b * N_ * N_;

    #pragma unroll 4
    for (int r = 0; r < 32; r++) {
        int kj = kjc + w * 32 + r;
        float v = 0.f;
        if (kj < KJ_ && i < N_) {
            int k = (kj >= 2000) ? 2 : (kj >= 1000 ? 1 : 0);
            int j = kj - k * 1000;
            v = __ldg(cheb + (size_t)kj * N_ + i) * __ldg(sb + (size_t)j * N_ + i);
        }
        buf[w * 32 + r][lane] = v;
    }
    __syncthreads();

    #pragma unroll
    for (int rr = 0; rr < 4; rr++) {
        int iw = i0 + w * 4 + rr;
        if (iw < N_) {
            float* __restrict__ outp = g_AT + ((size_t)b * MP_ + iw) * KJP_;
            #pragma unroll
            for (int c = 0; c < 8; c++) {
                int kj = kjc + c * 32 + lane;
                if (kj < KJ_)
                    outp[kj] = to_tf32(buf[c * 32 + lane][w * 4 + rr]);
            }
        }
    }
}

// ---------------------------------------------------------------------------
// Kernel 4: tensor-core GEMM (tf32 mma.sync)
//   D[b][i][to] = relu( sum_kj AT[b][i][kj] * yT[b][to][kj] )
// BM=128 (i) x BN=128 (to) x BK=32, 8 warps, warp-tile 32x64.
// ---------------------------------------------------------------------------
__global__ __launch_bounds__(256, 2) void k_spatial_tc(
    float* __restrict__ out)          // (B,T,N,OUT)
{
    __shared__ float As[128][36];     // [i-local][k-local], 36-pad -> ldmatrix conflict-free
    __shared__ float Bs[128][36];     // [to-local][k-local]

    const int b  = blockIdx.z;
    const int i0 = blockIdx.y * 128;
    const int n0 = blockIdx.x * 128;

    const int tid  = threadIdx.x;
    const int lane = tid & 31;
    const int w    = tid >> 5;
    const int im   = (w & 3) * 32;    // warp m-origin
    const int in_  = (w >> 2) * 64;   // warp n-origin

    const float* __restrict__ atp = g_AT + ((size_t)b * MP_ + i0) * KJP_;
    const float* __restrict__ ytp = g_yT + ((size_t)b * TO_ + n0) * KJP_;

    float c[2][8][4];
    #pragma unroll
    for (int mt = 0; mt < 2; mt++)
        #pragma unroll
        for (int nt = 0; nt < 8; nt++)
            #pragma unroll
            for (int q = 0; q < 4; q++) c[mt][nt][q] = 0.f;

    const uint32_t as_base = (uint32_t)__cvta_generic_to_shared(&As[0][0]);
    const uint32_t bs_base = (uint32_t)__cvta_generic_to_shared(&Bs[0][0]);

    // ldmatrix per-lane row/col offsets (x4 = four 8x4-tf32 matrices)
    // A: m0=[r0:8][c0:4] m1=[r8:16][c0:4] m2=[r0:8][c4:8] m3=[r8:16][c4:8]
    const int a_row  = lane & 15;
    const int a_col4 = (lane >> 4) * 4;
    // B: m0=[n0:8][c0:4] m1=[n0:8][c4:8] m2=[n8:16][c0:4] m3=[n8:16][c4:8]
    const int b_row  = (lane & 7) + ((lane & 16) >> 1);
    const int b_col4 = ((lane >> 3) & 1) * 4;

    for (int pc = 0; pc < KJP_ / 32; pc++) {
        const int p = pc * 32;
        #pragma unroll
        for (int l = 0; l < 4; l++) {
            int idx = tid + l * 256;          // 0..1023
            int row = idx >> 3;               // 0..127
            int c4  = (idx & 7) * 4;          // 0..28
            *(float4*)&As[row][c4] = *(const float4*)&atp[(size_t)row * KJP_ + p + c4];
            *(float4*)&Bs[row][c4] = *(const float4*)&ytp[(size_t)row * KJP_ + p + c4];
        }
        __syncthreads();

        #pragma unroll
        for (int ks = 0; ks < 4; ks++) {
            const int k0 = ks * 8;
            uint32_t a[2][4];
            #pragma unroll
            for (int mt = 0; mt < 2; mt++) {
                uint32_t addr = as_base +
                    (uint32_t)(((im + mt * 16 + a_row) * 36 + k0 + a_col4) * 4);
                asm volatile(
                    "ldmatrix.sync.aligned.m8n8.x4.shared.b16 {%0,%1,%2,%3}, [%4];"
                    : "=r"(a[mt][0]), "=r"(a[mt][1]), "=r"(a[mt][2]), "=r"(a[mt][3])
                    : "r"(addr));
            }
            uint32_t bb[8][2];
            #pragma unroll
            for (int nb = 0; nb < 4; nb++) {
                uint32_t addr = bs_base +
                    (uint32_t)(((in_ + nb * 16 + b_row) * 36 + k0 + b_col4) * 4);
                uint32_t r0, r1, r2, r3;
                asm volatile(
                    "ldmatrix.sync.aligned.m8n8.x4.shared.b16 {%0,%1,%2,%3}, [%4];"
                    : "=r"(r0), "=r"(r1), "=r"(r2), "=r"(r3)
                    : "r"(addr));
                bb[nb * 2][0] = r0; bb[nb * 2][1] = r1;
                bb[nb * 2 + 1][0] = r2; bb[nb * 2 + 1][1] = r3;
            }
            #pragma unroll
            for (int mt = 0; mt < 2; mt++)
                #pragma unroll
                for (int nt = 0; nt < 8; nt++)
                    asm volatile(
                        "mma.sync.aligned.m16n8k8.row.col.f32.tf32.tf32.f32 "
                        "{%0,%1,%2,%3}, {%4,%5,%6,%7}, {%8,%9}, {%0,%1,%2,%3};"
                        : "+f"(c[mt][nt][0]), "+f"(c[mt][nt][1]),
                          "+f"(c[mt][nt][2]), "+f"(c[mt][nt][3])
                        : "r"(a[mt][0]), "r"(a[mt][1]), "r"(a[mt][2]), "r"(a[mt][3]),
                          "r"(bb[nt][0]), "r"(bb[nt][1]));
        }
        __syncthreads();
    }

    // Epilogue: c0,c1 -> row gid; c2,c3 -> row gid+8; cols 2*tig, 2*tig+1
    const int gid = lane >> 2;
    const int tig = lane & 3;
    #pragma unroll
    for (int mt = 0; mt < 2; mt++) {
        #pragma unroll
        for (int half = 0; half < 2; half++) {
            const int i = i0 + im + mt * 16 + half * 8 + gid;
            if (i < N_) {
                #pragma unroll
                for (int nt = 0; nt < 8; nt++) {
                    const int to = n0 + in_ + nt * 8 + tig * 2;
                    const int t  = to >> 6;
                    const int o  = to & 63;
                    float2 v;
                    v.x = fmaxf(c[mt][nt][half * 2 + 0], 0.f);
                    v.y = fmaxf(c[mt][nt][half * 2 + 1], 0.f);
                    *(float2*)&out[(size_t)b * (T_ * N_ * OUT_) +
                                   (size_t)t * (N_ * OUT_) +
                                   (size_t)i * OUT_ + o] = v;
                }
            }
        }
    }
}

// ---------------------------------------------------------------------------
// Launch: inputs per metadata order: x, SAtt, cheb, Theta. Output float32.
// ---------------------------------------------------------------------------
extern "C" void kernel_launch(void* const* d_in, const int* in_sizes, int n_in,
                              void* d_out, int out_size)
{
    const float* x     = (const float*)d_in[0];
    const float* SAtt  = (const float*)d_in[1];
    const float* cheb  = (const float*)d_in[2];
    const float* Theta = (const float*)d_in[3];
    float* out = (float*)d_out;

    k_feature<<<(B_ * T_ * N_) / 16, 256>>>(x, Theta);
    k_transpose_y<<<dim3(94, 24, B_), 256>>>();
    k_buildA<<<dim3(12, 32, B_), 256>>>(SAtt, cheb);
    k_spatial_tc<<<dim3(TO_ / 128, MP_ / 128, B_), 256>>>(out);
}

// round 3
// speedup vs baseline: 3.4736x; 1.3219x over previous
#include <cuda_runtime.h>
#include <cstdint>

// Shapes (fixed by the problem)
#define B_   16
#define T_   12
#define N_   1000
#define F_   64
#define KC_  3
#define OUT_ 64

#define KJ_   3000            // contraction dim kj = k*1000 + j
#define KJP_  3008            // padded to multiple of 32
#define MP_   1024            // i padded
#define TO_   768             // t*64 + o

// Scratch (zero-initialized at module load; pad regions never written -> stay 0)
__device__ float g_ThT[KC_ * OUT_ * F_];          // ThT[(k*64+o)][f] (tf32)
__device__ float g_yT[(size_t)B_ * TO_ * KJP_];   // yT[b][to][kjp]  (tf32)
__device__ float g_AT[(size_t)B_ * MP_ * KJP_];   // AT[b][i][kjp]   (tf32)

__device__ __forceinline__ float to_tf32(float v) {
    uint32_t u;
    asm("cvt.rna.tf32.f32 %0, %1;" : "=r"(u) : "f"(v));
    return __uint_as_float(u);
}

__device__ __forceinline__ void cpasync16(uint32_t dst, const float* src) {
    asm volatile("cp.async.cg.shared.global [%0], [%1], 16;" :: "r"(dst), "l"(src));
}

// ---------------------------------------------------------------------------
// Kernel 0: ThT[(k*64+o)][f] = tf32(Theta[k,f,o])   (tiny transpose, 1 block)
// ---------------------------------------------------------------------------
__global__ __launch_bounds__(256) void k_thetaT(const float* __restrict__ Theta)
{
    for (int idx = threadIdx.x; idx < KC_ * OUT_ * F_; idx += 256) {
        const int f  = idx & 63;
        const int ko = idx >> 6;          // k*64 + o
        const int k  = ko >> 6;
        const int o  = ko & 63;
        g_ThT[idx] = to_tf32(Theta[(k * F_ + f) * OUT_ + o]);
    }
}

// ---------------------------------------------------------------------------
// Kernel 1: feature transform, transposed output, tensor cores.
//   For each (b,t):  C[(k*64+o)][j] = sum_f ThT[(ko)][f] * x[b,t,j,f]
//   written as yT[b][t*64+o][k*1000+j]  (kj-contiguous, coalesced)
// BM=64 (ko), BN=128 (j), K=64 (2 k-tiles of 32). 8 warps = 2m x 4n.
// ---------------------------------------------------------------------------
__global__ __launch_bounds__(256) void k_featT_tc(const float* __restrict__ x)
{
    __shared__ float As[64][36];
    __shared__ float Bs[128][36];

    const int j0 = blockIdx.x * 128;
    const int m0 = blockIdx.y * 64;       // ko origin (0,64,128)
    const int bt = blockIdx.z;
    const int b  = bt / T_;
    const int t  = bt % T_;

    const int tid  = threadIdx.x;
    const int lane = tid & 31;
    const int w    = tid >> 5;
    const int wm   = (w & 1) * 32;
    const int wn   = (w >> 1) * 32;

    const float* __restrict__ xp = x + (size_t)bt * N_ * F_;

    float c[2][4][4];
    #pragma unroll
    for (int mt = 0; mt < 2; mt++)
        #pragma unroll
        for (int nt = 0; nt < 4; nt++)
            #pragma unroll
            for (int q = 0; q < 4; q++) c[mt][nt][q] = 0.f;

    const uint32_t as_base = (uint32_t)__cvta_generic_to_shared(&As[0][0]);
    const uint32_t bs_base = (uint32_t)__cvta_generic_to_shared(&Bs[0][0]);

    const int a_row  = lane & 15;
    const int a_col4 = (lane >> 4) * 4;
    const int b_row  = (lane & 7) + ((lane & 16) >> 1);
    const int b_col4 = ((lane >> 3) & 1) * 4;

    #pragma unroll
    for (int kt = 0; kt < 2; kt++) {
        const int f0 = kt * 32;
        // load A tile: ThT rows m0..m0+63, cols f0..f0+31 (already tf32)
        #pragma unroll
        for (int l = 0; l < 2; l++) {
            int idx = tid + l * 256;
            int row = idx >> 3, c4 = (idx & 7) * 4;
            *(float4*)&As[row][c4] = *(const float4*)&g_ThT[(m0 + row) * F_ + f0 + c4];
        }
        // load B tile: x rows j0..j0+127, cols f0..f0+31, round to tf32
        #pragma unroll
        for (int l = 0; l < 4; l++) {
            int idx = tid + l * 256;
            int row = idx >> 3, c4 = (idx & 7) * 4;
            float4 v;
            if (j0 + row < N_) {
                v = *(const float4*)&xp[(size_t)(j0 + row) * F_ + f0 + c4];
                v.x = to_tf32(v.x); v.y = to_tf32(v.y);
                v.z = to_tf32(v.z); v.w = to_tf32(v.w);
            } else {
                v = make_float4(0.f, 0.f, 0.f, 0.f);
            }
            *(float4*)&Bs[row][c4] = v;
        }
        __syncthreads();

        #pragma unroll
        for (int ks = 0; ks < 4; ks++) {
            const int k0 = ks * 8;
            uint32_t a[2][4];
            #pragma unroll
            for (int mt = 0; mt < 2; mt++) {
                uint32_t addr = as_base +
                    (uint32_t)(((wm + mt * 16 + a_row) * 36 + k0 + a_col4) * 4);
                asm volatile(
                    "ldmatrix.sync.aligned.m8n8.x4.shared.b16 {%0,%1,%2,%3}, [%4];"
                    : "=r"(a[mt][0]), "=r"(a[mt][1]), "=r"(a[mt][2]), "=r"(a[mt][3])
                    : "r"(addr));
            }
            uint32_t bb[4][2];
            #pragma unroll
            for (int nb = 0; nb < 2; nb++) {
                uint32_t addr = bs_base +
                    (uint32_t)(((wn + nb * 16 + b_row) * 36 + k0 + b_col4) * 4);
                uint32_t r0, r1, r2, r3;
                asm volatile(
                    "ldmatrix.sync.aligned.m8n8.x4.shared.b16 {%0,%1,%2,%3}, [%4];"
                    : "=r"(r0), "=r"(r1), "=r"(r2), "=r"(r3)
                    : "r"(addr));
                bb[nb * 2][0] = r0;     bb[nb * 2][1] = r1;
                bb[nb * 2 + 1][0] = r2; bb[nb * 2 + 1][1] = r3;
            }
            #pragma unroll
            for (int mt = 0; mt < 2; mt++)
                #pragma unroll
                for (int nt = 0; nt < 4; nt++)
                    asm volatile(
                        "mma.sync.aligned.m16n8k8.row.col.f32.tf32.tf32.f32 "
                        "{%0,%1,%2,%3}, {%4,%5,%6,%7}, {%8,%9}, {%0,%1,%2,%3};"
                        : "+f"(c[mt][nt][0]), "+f"(c[mt][nt][1]),
                          "+f"(c[mt][nt][2]), "+f"(c[mt][nt][3])
                        : "r"(a[mt][0]), "r"(a[mt][1]), "r"(a[mt][2]), "r"(a[mt][3]),
                          "r"(bb[nt][0]), "r"(bb[nt][1]));
        }
        __syncthreads();
    }

    // Epilogue: row ko -> (k,o); col j. Write tf32(yT[b][t*64+o][k*1000+j]).
    const int gid = lane >> 2;
    const int tig = lane & 3;
    #pragma unroll
    for (int mt = 0; mt < 2; mt++) {
        #pragma unroll
        for (int half = 0; half < 2; half++) {
            const int ko = m0 + wm + mt * 16 + half * 8 + gid;
            const int k  = ko >> 6;
            const int o  = ko & 63;
            float* __restrict__ dst =
                g_yT + ((size_t)b * TO_ + t * OUT_ + o) * KJP_ + k * N_;
            #pragma unroll
            for (int nt = 0; nt < 4; nt++) {
                const int j = j0 + wn + nt * 8 + tig * 2;
                if (j < N_) {
                    float2 v;
                    v.x = to_tf32(c[mt][nt][half * 2 + 0]);
                    v.y = to_tf32(c[mt][nt][half * 2 + 1]);
                    *(float2*)&dst[j] = v;
                }
            }
        }
    }
}

// ---------------------------------------------------------------------------
// Kernel 2: AT[b][i][kj] = tf32( cheb[kj,i] * SAtt[b, kj%1000, i] )
// ---------------------------------------------------------------------------
__global__ __launch_bounds__(256) void k_buildA(
    const float* __restrict__ SAtt,   // (B,N,N)
    const float* __restrict__ cheb)   // (K,N,N)
{
    __shared__ float buf[256][33];    // [kj-local][i-local(32)]
    const int b    = blockIdx.z;
    const int i0   = blockIdx.y * 32;
    const int kjc  = blockIdx.x * 256;
    const int lane = threadIdx.x & 31;
    const int w    = threadIdx.x >> 5;
    const int i    = i0 + lane;

    const float* __restrict__ sb = SAtt + (size_t)b * N_ * N_;

    #pragma unroll 4
    for (int r = 0; r < 32; r++) {
        int kj = kjc + w * 32 + r;
        float v = 0.f;
        if (kj < KJ_ && i < N_) {
            int k = (kj >= 2000) ? 2 : (kj >= 1000 ? 1 : 0);
            int j = kj - k * 1000;
            v = __ldg(cheb + (size_t)kj * N_ + i) * __ldg(sb + (size_t)j * N_ + i);
        }
        buf[w * 32 + r][lane] = v;
    }
    __syncthreads();

    #pragma unroll
    for (int rr = 0; rr < 4; rr++) {
        int iw = i0 + w * 4 + rr;
        if (iw < N_) {
            float* __restrict__ outp = g_AT + ((size_t)b * MP_ + iw) * KJP_;
            #pragma unroll
            for (int c = 0; c < 8; c++) {
                int kj = kjc + c * 32 + lane;
                if (kj < KJ_)
                    outp[kj] = to_tf32(buf[c * 32 + lane][w * 4 + rr]);
            }
        }
    }
}

// ---------------------------------------------------------------------------
// Kernel 3: spatial GEMM, tf32 mma, cp.async double-buffered (BK=16, 2-stage)
//   D[b][i][to] = relu( sum_kj AT[b][i][kj] * yT[b][to][kj] )
// ---------------------------------------------------------------------------
#define SBK 16
#define NTILE (KJP_ / SBK)    // 188

__global__ __launch_bounds__(256, 2) void k_spatial_tc(
    float* __restrict__ out)          // (B,T,N,OUT)
{
    __shared__ float As[2][128][20];  // 20-pad: rows 16B-aligned, LDSM conflict-free
    __shared__ float Bs[2][128][20];

    const int b  = blockIdx.z;
    const int i0 = blockIdx.y * 128;
    const int n0 = blockIdx.x * 128;

    const int tid  = threadIdx.x;
    const int lane = tid & 31;
    const int w    = tid >> 5;
    const int im   = (w & 3) * 32;
    const int in_  = (w >> 2) * 64;

    const float* __restrict__ atp = g_AT + ((size_t)b * MP_ + i0) * KJP_;
    const float* __restrict__ ytp = g_yT + ((size_t)b * TO_ + n0) * KJP_;

    float c[2][8][4];
    #pragma unroll
    for (int mt = 0; mt < 2; mt++)
        #pragma unroll
        for (int nt = 0; nt < 8; nt++)
            #pragma unroll
            for (int q = 0; q < 4; q++) c[mt][nt][q] = 0.f;

    const uint32_t as_base = (uint32_t)__cvta_generic_to_shared(&As[0][0][0]);
    const uint32_t bs_base = (uint32_t)__cvta_generic_to_shared(&Bs[0][0][0]);

    // per-thread load slots: 512 float4 per operand, 2 per thread
    const int ld_row0 = tid >> 2;                 // 0..63
    const int ld_c4   = (tid & 3) * 4;            // 0,4,8,12

    const int a_row  = lane & 15;
    const int a_col4 = (lane >> 4) * 4;
    const int b_row  = (lane & 7) + ((lane & 16) >> 1);
    const int b_col4 = ((lane >> 3) & 1) * 4;

    // ---- prologue: load tile 0 into buf 0
    #pragma unroll
    for (int l = 0; l < 2; l++) {
        const int row = ld_row0 + l * 64;
        const uint32_t so = (uint32_t)((row * 20 + ld_c4) * 4);
        cpasync16(as_base + so, atp + (size_t)row * KJP_ + ld_c4);
        cpasync16(bs_base + so, ytp + (size_t)row * KJP_ + ld_c4);
    }
    asm volatile("cp.async.commit_group;");

    for (int pc = 0; pc < NTILE; pc++) {
        const int cur = pc & 1;
        if (pc + 1 < NTILE) {
            const int p1 = (pc + 1) * SBK;
            const uint32_t bo = (uint32_t)((cur ^ 1) * 128 * 20 * 4);
            #pragma unroll
            for (int l = 0; l < 2; l++) {
                const int row = ld_row0 + l * 64;
                const uint32_t so = bo + (uint32_t)((row * 20 + ld_c4) * 4);
                cpasync16(as_base + so, atp + (size_t)row * KJP_ + p1 + ld_c4);
                cpasync16(bs_base + so, ytp + (size_t)row * KJP_ + p1 + ld_c4);
            }
            asm volatile("cp.async.commit_group;");
            asm volatile("cp.async.wait_group 1;");
        } else {
            asm volatile("cp.async.wait_group 0;");
        }
        __syncthreads();

        const uint32_t bo = (uint32_t)(cur * 128 * 20 * 4);
        #pragma unroll
        for (int ks = 0; ks < 2; ks++) {
            const int k0 = ks * 8;
            uint32_t a[2][4];
            #pragma unroll
            for (int mt = 0; mt < 2; mt++) {
                uint32_t addr = as_base + bo +
                    (uint32_t)(((im + mt * 16 + a_row) * 20 + k0 + a_col4) * 4);
                asm volatile(
                    "ldmatrix.sync.aligned.m8n8.x4.shared.b16 {%0,%1,%2,%3}, [%4];"
                    : "=r"(a[mt][0]), "=r"(a[mt][1]), "=r"(a[mt][2]), "=r"(a[mt][3])
                    : "r"(addr));
            }
            uint32_t bb[8][2];
            #pragma unroll
            for (int nb = 0; nb < 4; nb++) {
                uint32_t addr = bs_base + bo +
                    (uint32_t)(((in_ + nb * 16 + b_row) * 20 + k0 + b_col4) * 4);
                uint32_t r0, r1, r2, r3;
                asm volatile(
                    "ldmatrix.sync.aligned.m8n8.x4.shared.b16 {%0,%1,%2,%3}, [%4];"
                    : "=r"(r0), "=r"(r1), "=r"(r2), "=r"(r3)
                    : "r"(addr));
                bb[nb * 2][0] = r0;     bb[nb * 2][1] = r1;
                bb[nb * 2 + 1][0] = r2; bb[nb * 2 + 1][1] = r3;
            }
            #pragma unroll
            for (int mt = 0; mt < 2; mt++)
                #pragma unroll
                for (int nt = 0; nt < 8; nt++)
                    asm volatile(
                        "mma.sync.aligned.m16n8k8.row.col.f32.tf32.tf32.f32 "
                        "{%0,%1,%2,%3}, {%4,%5,%6,%7}, {%8,%9}, {%0,%1,%2,%3};"
                        : "+f"(c[mt][nt][0]), "+f"(c[mt][nt][1]),
                          "+f"(c[mt][nt][2]), "+f"(c[mt][nt][3])
                        : "r"(a[mt][0]), "r"(a[mt][1]), "r"(a[mt][2]), "r"(a[mt][3]),
                          "r"(bb[nt][0]), "r"(bb[nt][1]));
        }
        __syncthreads();
    }

    // Epilogue with fused relu
    const int gid = lane >> 2;
    const int tig = lane & 3;
    #pragma unroll
    for (int mt = 0; mt < 2; mt++) {
        #pragma unroll
        for (int half = 0; half < 2; half++) {
            const int i = i0 + im + mt * 16 + half * 8 + gid;
            if (i < N_) {
                #pragma unroll
                for (int nt = 0; nt < 8; nt++) {
                    const int to = n0 + in_ + nt * 8 + tig * 2;
                    const int t  = to >> 6;
                    const int o  = to & 63;
                    float2 v;
                    v.x = fmaxf(c[mt][nt][half * 2 + 0], 0.f);
                    v.y = fmaxf(c[mt][nt][half * 2 + 1], 0.f);
                    *(float2*)&out[(size_t)b * (T_ * N_ * OUT_) +
                                   (size_t)t * (N_ * OUT_) +
                                   (size_t)i * OUT_ + o] = v;
                }
            }
        }
    }
}

// ---------------------------------------------------------------------------
// Launch: inputs per metadata order: x, SAtt, cheb, Theta. Output float32.
// ---------------------------------------------------------------------------
extern "C" void kernel_launch(void* const* d_in, const int* in_sizes, int n_in,
                              void* d_out, int out_size)
{
    const float* x     = (const float*)d_in[0];
    const float* SAtt  = (const float*)d_in[1];
    const float* cheb  = (const float*)d_in[2];
    const float* Theta = (const float*)d_in[3];
    float* out = (float*)d_out;

    k_thetaT<<<1, 256>>>(Theta);
    k_featT_tc<<<dim3(8, 3, B_ * T_), 256>>>(x);
    k_buildA<<<dim3(12, 32, B_), 256>>>(SAtt, cheb);
    k_spatial_tc<<<dim3(TO_ / 128, MP_ / 128, B_), 256>>>(out);
}

// round 5
// speedup vs baseline: 3.9819x; 1.1463x over previous
#include <cuda_runtime.h>
#include <cstdint>

// Shapes (fixed by the problem)
#define B_   16
#define T_   12
#define N_   1000
#define F_   64
#define KC_  3
#define OUT_ 64

#define KJ_   3000            // contraction dim kj = k*1000 + j
#define KJP_  3008            // padded to multiple of 32
#define MP_   1024            // i padded
#define TO_   768             // t*64 + o

// Scratch (zero-initialized at module load; pad regions never written -> stay 0)
__device__ __align__(256) float g_ThT[KC_ * OUT_ * F_];          // ThT[(k*64+o)][f]
__device__ __align__(256) float g_yT[(size_t)B_ * TO_ * KJP_];   // yT[b][to][kjp]
__device__ __align__(256) float g_AT[(size_t)B_ * MP_ * KJP_];   // AT[b][i][kjp]

__device__ __forceinline__ float to_tf32(float v) {
    uint32_t u;
    asm("cvt.rna.tf32.f32 %0, %1;" : "=r"(u) : "f"(v));
    return __uint_as_float(u);
}

__device__ __forceinline__ void cpasync16(uint32_t dst, const float* src) {
    asm volatile("cp.async.cg.shared.global [%0], [%1], 16;" :: "r"(dst), "l"(src));
}

__device__ __forceinline__ uint32_t smem_u32(const void* p) {
    uint32_t a;
    asm("{ .reg .u64 t; cvta.to.shared.u64 t, %1; cvt.u32.u64 %0, t; }"
        : "=r"(a) : "l"(p));
    return a;
}

// ---------------------------------------------------------------------------
// Kernel 0: ThT[(k*64+o)][f] = tf32(Theta[k,f,o])
// ---------------------------------------------------------------------------
__global__ __launch_bounds__(256) void k_thetaT(const float* __restrict__ Theta)
{
    for (int idx = threadIdx.x; idx < KC_ * OUT_ * F_; idx += 256) {
        const int f  = idx & 63;
        const int ko = idx >> 6;
        const int k  = ko >> 6;
        const int o  = ko & 63;
        g_ThT[idx] = to_tf32(Theta[(k * F_ + f) * OUT_ + o]);
    }
}

// ---------------------------------------------------------------------------
// Kernel 1: feature transform (mma.sync tf32), transposed output (kj-contig)
//   yT[b][t*64+o][k*1000+j] = sum_f ThT[(k*64+o)][f] * x[b,t,j,f]
// ---------------------------------------------------------------------------
__global__ __launch_bounds__(256) void k_featT_tc(const float* __restrict__ x)
{
    __shared__ float As[64][36];
    __shared__ float Bs[128][36];

    const int j0 = blockIdx.x * 128;
    const int m0 = blockIdx.y * 64;
    const int bt = blockIdx.z;
    const int b  = bt / T_;
    const int t  = bt % T_;

    const int tid  = threadIdx.x;
    const int lane = tid & 31;
    const int w    = tid >> 5;
    const int wm   = (w & 1) * 32;
    const int wn   = (w >> 1) * 32;

    const float* __restrict__ xp = x + (size_t)bt * N_ * F_;

    float c[2][4][4];
    #pragma unroll
    for (int mt = 0; mt < 2; mt++)
        #pragma unroll
        for (int nt = 0; nt < 4; nt++)
            #pragma unroll
            for (int q = 0; q < 4; q++) c[mt][nt][q] = 0.f;

    const uint32_t as_base = smem_u32(&As[0][0]);
    const uint32_t bs_base = smem_u32(&Bs[0][0]);

    const int a_row  = lane & 15;
    const int a_col4 = (lane >> 4) * 4;
    const int b_row  = (lane & 7) + ((lane & 16) >> 1);
    const int b_col4 = ((lane >> 3) & 1) * 4;

    #pragma unroll
    for (int kt = 0; kt < 2; kt++) {
        const int f0 = kt * 32;
        #pragma unroll
        for (int l = 0; l < 2; l++) {
            int idx = tid + l * 256;
            int row = idx >> 3, c4 = (idx & 7) * 4;
            *(float4*)&As[row][c4] = *(const float4*)&g_ThT[(m0 + row) * F_ + f0 + c4];
        }
        #pragma unroll
        for (int l = 0; l < 4; l++) {
            int idx = tid + l * 256;
            int row = idx >> 3, c4 = (idx & 7) * 4;
            float4 v;
            if (j0 + row < N_) {
                v = *(const float4*)&xp[(size_t)(j0 + row) * F_ + f0 + c4];
                v.x = to_tf32(v.x); v.y = to_tf32(v.y);
                v.z = to_tf32(v.z); v.w = to_tf32(v.w);
            } else {
                v = make_float4(0.f, 0.f, 0.f, 0.f);
            }
            *(float4*)&Bs[row][c4] = v;
        }
        __syncthreads();

        #pragma unroll
        for (int ks = 0; ks < 4; ks++) {
            const int k0 = ks * 8;
            uint32_t a[2][4];
            #pragma unroll
            for (int mt = 0; mt < 2; mt++) {
                uint32_t addr = as_base +
                    (uint32_t)(((wm + mt * 16 + a_row) * 36 + k0 + a_col4) * 4);
                asm volatile(
                    "ldmatrix.sync.aligned.m8n8.x4.shared.b16 {%0,%1,%2,%3}, [%4];"
                    : "=r"(a[mt][0]), "=r"(a[mt][1]), "=r"(a[mt][2]), "=r"(a[mt][3])
                    : "r"(addr));
            }
            uint32_t bb[4][2];
            #pragma unroll
            for (int nb = 0; nb < 2; nb++) {
                uint32_t addr = bs_base +
                    (uint32_t)(((wn + nb * 16 + b_row) * 36 + k0 + b_col4) * 4);
                uint32_t r0, r1, r2, r3;
                asm volatile(
                    "ldmatrix.sync.aligned.m8n8.x4.shared.b16 {%0,%1,%2,%3}, [%4];"
                    : "=r"(r0), "=r"(r1), "=r"(r2), "=r"(r3)
                    : "r"(addr));
                bb[nb * 2][0] = r0;     bb[nb * 2][1] = r1;
                bb[nb * 2 + 1][0] = r2; bb[nb * 2 + 1][1] = r3;
            }
            #pragma unroll
            for (int mt = 0; mt < 2; mt++)
                #pragma unroll
                for (int nt = 0; nt < 4; nt++)
                    asm volatile(
                        "mma.sync.aligned.m16n8k8.row.col.f32.tf32.tf32.f32 "
                        "{%0,%1,%2,%3}, {%4,%5,%6,%7}, {%8,%9}, {%0,%1,%2,%3};"
                        : "+f"(c[mt][nt][0]), "+f"(c[mt][nt][1]),
                          "+f"(c[mt][nt][2]), "+f"(c[mt][nt][3])
                        : "r"(a[mt][0]), "r"(a[mt][1]), "r"(a[mt][2]), "r"(a[mt][3]),
                          "r"(bb[nt][0]), "r"(bb[nt][1]));
        }
        __syncthreads();
    }

    const int gid = lane >> 2;
    const int tig = lane & 3;
    #pragma unroll
    for (int mt = 0; mt < 2; mt++) {
        #pragma unroll
        for (int half = 0; half < 2; half++) {
            const int ko = m0 + wm + mt * 16 + half * 8 + gid;
            const int k  = ko >> 6;
            const int o  = ko & 63;
            float* __restrict__ dst =
                g_yT + ((size_t)b * TO_ + t * OUT_ + o) * KJP_ + k * N_;
            #pragma unroll
            for (int nt = 0; nt < 4; nt++) {
                const int j = j0 + wn + nt * 8 + tig * 2;
                if (j < N_) {
                    float2 v;
                    v.x = to_tf32(c[mt][nt][half * 2 + 0]);
                    v.y = to_tf32(c[mt][nt][half * 2 + 1]);
                    *(float2*)&dst[j] = v;
                }
            }
        }
    }
}

// ---------------------------------------------------------------------------
// Kernel 2: AT[b][i][kj] = tf32( cheb[kj,i] * SAtt[b, kj%1000, i] )
// ---------------------------------------------------------------------------
__global__ __launch_bounds__(256) void k_buildA(
    const float* __restrict__ SAtt,
    const float* __restrict__ cheb)
{
    __shared__ float buf[256][33];
    const int b    = blockIdx.z;
    const int i0   = blockIdx.y * 32;
    const int kjc  = blockIdx.x * 256;
    const int lane = threadIdx.x & 31;
    const int w    = threadIdx.x >> 5;
    const int i    = i0 + lane;

    const float* __restrict__ sb = SAtt + (size_t)b * N_ * N_;

    #pragma unroll 4
    for (int r = 0; r < 32; r++) {
        int kj = kjc + w * 32 + r;
        float v = 0.f;
        if (kj < KJ_ && i < N_) {
            int k = (kj >= 2000) ? 2 : (kj >= 1000 ? 1 : 0);
            int j = kj - k * 1000;
            v = __ldg(cheb + (size_t)kj * N_ + i) * __ldg(sb + (size_t)j * N_ + i);
        }
        buf[w * 32 + r][lane] = v;
    }
    __syncthreads();

    #pragma unroll
    for (int rr = 0; rr < 4; rr++) {
        int iw = i0 + w * 4 + rr;
        if (iw < N_) {
            float* __restrict__ outp = g_AT + ((size_t)b * MP_ + iw) * KJP_;
            #pragma unroll
            for (int c = 0; c < 8; c++) {
                int kj = kjc + c * 32 + lane;
                if (kj < KJ_)
                    outp[kj] = to_tf32(buf[c * 32 + lane][w * 4 + rr]);
            }
        }
    }
}

// ---------------------------------------------------------------------------
// Kernel 3: spatial GEMM, tf32 mma.sync, BK=32, cp.async double-buffered,
// one __syncthreads per tile.
//   D[b][i][to] = relu( sum_kj AT[b][i][kj] * yT[b][to][kj] )
// ---------------------------------------------------------------------------
#define SBK    32
#define NTILE  (KJP_ / SBK)          // 94
#define STG_F  (128 * 36)            // floats per stage per operand

__global__ __launch_bounds__(256, 2) void k_spatial_db(float* __restrict__ out)
{
    extern __shared__ float sm[];
    float* Asm = sm;                  // [2][128][36]
    float* Bsm = sm + 2 * STG_F;      // [2][128][36]

    const int b  = blockIdx.z;
    const int i0 = blockIdx.y * 128;
    const int n0 = blockIdx.x * 128;

    const int tid  = threadIdx.x;
    const int lane = tid & 31;
    const int w    = tid >> 5;
    const int im   = (w & 3) * 32;
    const int in_  = (w >> 2) * 64;

    const float* __restrict__ atp = g_AT + ((size_t)b * MP_ + i0) * KJP_;
    const float* __restrict__ ytp = g_yT + ((size_t)b * TO_ + n0) * KJP_;

    float c[2][8][4];
    #pragma unroll
    for (int mt = 0; mt < 2; mt++)
        #pragma unroll
        for (int nt = 0; nt < 8; nt++)
            #pragma unroll
            for (int q = 0; q < 4; q++) c[mt][nt][q] = 0.f;

    const uint32_t as_base = smem_u32(Asm);
    const uint32_t bs_base = smem_u32(Bsm);

    // load geometry: 1024 16B-chunks per operand-tile, 4 per thread
    const int ld_row = tid >> 3;          // 0..31 (+32*l)
    const int ld_c4  = (tid & 7) * 4;     // 0..28

    const int a_row  = lane & 15;
    const int a_col4 = (lane >> 4) * 4;
    const int b_row  = (lane & 7) + ((lane & 16) >> 1);
    const int b_col4 = ((lane >> 3) & 1) * 4;

    // prologue: tile 0 -> stage 0
    #pragma unroll
    for (int l = 0; l < 4; l++) {
        const int row = ld_row + l * 32;
        const uint32_t so = (uint32_t)((row * 36 + ld_c4) * 4);
        cpasync16(as_base + so, atp + (size_t)row * KJP_ + ld_c4);
        cpasync16(bs_base + so, ytp + (size_t)row * KJP_ + ld_c4);
    }
    asm volatile("cp.async.commit_group;");

    for (int pc = 0; pc < NTILE; pc++) {
        const int cur = pc & 1;
        asm volatile("cp.async.wait_group 0;");
        __syncthreads();

        // prefetch tile pc+1 into the other stage (overlaps compute below)
        if (pc + 1 < NTILE) {
            const int p1 = (pc + 1) * SBK;
            const uint32_t nbo = (uint32_t)((cur ^ 1) * STG_F * 4);
            #pragma unroll
            for (int l = 0; l < 4; l++) {
                const int row = ld_row + l * 32;
                const uint32_t so = nbo + (uint32_t)((row * 36 + ld_c4) * 4);
                cpasync16(as_base + so, atp + (size_t)row * KJP_ + p1 + ld_c4);
                cpasync16(bs_base + so, ytp + (size_t)row * KJP_ + p1 + ld_c4);
            }
            asm volatile("cp.async.commit_group;");
        }

        const uint32_t bo = (uint32_t)(cur * STG_F * 4);
        #pragma unroll
        for (int ks = 0; ks < 4; ks++) {
            const int k0 = ks * 8;
            uint32_t a[2][4];
            #pragma unroll
            for (int mt = 0; mt < 2; mt++) {
                uint32_t addr = as_base + bo +
                    (uint32_t)(((im + mt * 16 + a_row) * 36 + k0 + a_col4) * 4);
                asm volatile(
                    "ldmatrix.sync.aligned.m8n8.x4.shared.b16 {%0,%1,%2,%3}, [%4];"
                    : "=r"(a[mt][0]), "=r"(a[mt][1]), "=r"(a[mt][2]), "=r"(a[mt][3])
                    : "r"(addr));
            }
            uint32_t bb[8][2];
            #pragma unroll
            for (int nb = 0; nb < 4; nb++) {
                uint32_t addr = bs_base + bo +
                    (uint32_t)(((in_ + nb * 16 + b_row) * 36 + k0 + b_col4) * 4);
                uint32_t r0, r1, r2, r3;
                asm volatile(
                    "ldmatrix.sync.aligned.m8n8.x4.shared.b16 {%0,%1,%2,%3}, [%4];"
                    : "=r"(r0), "=r"(r1), "=r"(r2), "=r"(r3)
                    : "r"(addr));
                bb[nb * 2][0] = r0;     bb[nb * 2][1] = r1;
                bb[nb * 2 + 1][0] = r2; bb[nb * 2 + 1][1] = r3;
            }
            #pragma unroll
            for (int mt = 0; mt < 2; mt++)
                #pragma unroll
                for (int nt = 0; nt < 8; nt++)
                    asm volatile(
                        "mma.sync.aligned.m16n8k8.row.col.f32.tf32.tf32.f32 "
                        "{%0,%1,%2,%3}, {%4,%5,%6,%7}, {%8,%9}, {%0,%1,%2,%3};"
                        : "+f"(c[mt][nt][0]), "+f"(c[mt][nt][1]),
                          "+f"(c[mt][nt][2]), "+f"(c[mt][nt][3])
                        : "r"(a[mt][0]), "r"(a[mt][1]), "r"(a[mt][2]), "r"(a[mt][3]),
                          "r"(bb[nt][0]), "r"(bb[nt][1]));
        }
        __syncthreads();
    }

    // Epilogue with fused relu
    const int gid = lane >> 2;
    const int tig = lane & 3;
    #pragma unroll
    for (int mt = 0; mt < 2; mt++) {
        #pragma unroll
        for (int half = 0; half < 2; half++) {
            const int i = i0 + im + mt * 16 + half * 8 + gid;
            if (i < N_) {
                #pragma unroll
                for (int nt = 0; nt < 8; nt++) {
                    const int to = n0 + in_ + nt * 8 + tig * 2;
                    const int t  = to >> 6;
                    const int o  = to & 63;
                    float2 v;
                    v.x = fmaxf(c[mt][nt][half * 2 + 0], 0.f);
                    v.y = fmaxf(c[mt][nt][half * 2 + 1], 0.f);
                    *(float2*)&out[(size_t)b * (T_ * N_ * OUT_) +
                                   (size_t)t * (N_ * OUT_) +
                                   (size_t)i * OUT_ + o] = v;
                }
            }
        }
    }
}

// ---------------------------------------------------------------------------
// Launch
// ---------------------------------------------------------------------------
extern "C" void kernel_launch(void* const* d_in, const int* in_sizes, int n_in,
                              void* d_out, int out_size)
{
    const float* x     = (const float*)d_in[0];
    const float* SAtt  = (const float*)d_in[1];
    const float* cheb  = (const float*)d_in[2];
    const float* Theta = (const float*)d_in[3];
    float* out = (float*)d_out;

    const int smem_db = 4 * STG_F * sizeof(float);   // 73728 B
    cudaFuncSetAttribute(k_spatial_db,
                         cudaFuncAttributeMaxDynamicSharedMemorySize, smem_db);

    k_thetaT<<<1, 256>>>(Theta);
    k_featT_tc<<<dim3(8, 3, B_ * T_), 256>>>(x);
    k_buildA<<<dim3(12, 32, B_), 256>>>(SAtt, cheb);
    k_spatial_db<<<dim3(TO_ / 128, MP_ / 128, B_), 256, smem_db>>>(out);
}